// round 13
// baseline (speedup 1.0000x reference)
#include <cuda_runtime.h>
#include <cstdint>
#include <cfloat>

// Problem constants
#define B_SZ   4
#define S_LEN  1024
#define NTOK   16
#define DMODEL 512
#define NH     8
#define HDIM   64
#define M_ROWS (B_SZ * S_LEN * NTOK)   // 65536
#define QKV_COLS (3 * NH * HDIM)       // 1536

// Scratch (allocation-free rule: __device__ globals)
__device__ float g_qkv[(size_t)M_ROWS * QKV_COLS];   // 402 MB (focus rows left unwritten/unused)
__device__ float g_ctx[(size_t)M_ROWS * DMODEL];     // 128 MB (non-focus rows only)
__device__ float g_wcomb[DMODEL * DMODEL];           // 1 MB: Wqkv_V @ Wout
__device__ int   g_focus[B_SZ];

// ---------------------------------------------------------------------------
// Mask decode (bool may arrive as u8 / i32 / f32) -> g_focus
// ---------------------------------------------------------------------------
__global__ void decode_mask(const unsigned char* __restrict__ fmask)
{
    const uint32_t* fw = reinterpret_cast<const uint32_t*>(fmask);
    uint32_t w[4] = {fw[0], fw[1], fw[2], fw[3]};
    bool is_f32 = true, is_i32 = true;
#pragma unroll
    for (int i = 0; i < 4; i++) {
        is_f32 &= (w[i] == 0u || w[i] == 0x3F800000u);
        is_i32 &= (w[i] <= 1u);
    }
#pragma unroll
    for (int b = 0; b < 4; b++)
        g_focus[b] = (is_f32 || is_i32) ? (w[b] != 0u) : (fmask[b] != 0);
}

// ---------------------------------------------------------------------------
// Small 64x64x16 SGEMM for Wcomb = Wqkv[:,1024:] @ Wout (512x512x512).
// 64 blocks -> one wave across the chip. A has row stride lda.
// ---------------------------------------------------------------------------
__global__ __launch_bounds__(256) void sgemm64(
    const float* __restrict__ A, int lda,
    const float* __restrict__ B,
    float* __restrict__ C, int N, int K)
{
    constexpr int BM = 64, BN = 64, BK = 16;
    __shared__ float As[BK][68];
    __shared__ float Bs[BK][68];

    const int tid = threadIdx.x;
    const int tx = tid & 15, ty = tid >> 4;
    const int row0 = blockIdx.y * BM, col0 = blockIdx.x * BN;
    const int a_r = tid >> 2, a_c = (tid & 3) << 2;
    const int b_r = tid >> 4, b_c = (tid & 15) << 2;

    float acc[4][4];
#pragma unroll
    for (int i = 0; i < 4; i++)
#pragma unroll
        for (int j = 0; j < 4; j++) acc[i][j] = 0.f;

    for (int k0 = 0; k0 < K; k0 += BK) {
        float4 va = *reinterpret_cast<const float4*>(A + (size_t)(row0 + a_r) * lda + k0 + a_c);
        As[a_c + 0][a_r] = va.x; As[a_c + 1][a_r] = va.y;
        As[a_c + 2][a_r] = va.z; As[a_c + 3][a_r] = va.w;
        *reinterpret_cast<float4*>(&Bs[b_r][b_c]) =
            *reinterpret_cast<const float4*>(B + (size_t)(k0 + b_r) * N + col0 + b_c);
        __syncthreads();
#pragma unroll
        for (int kk = 0; kk < BK; kk++) {
            float4 ra = *reinterpret_cast<const float4*>(&As[kk][ty * 4]);
            float4 rb = *reinterpret_cast<const float4*>(&Bs[kk][tx * 4]);
            float a4[4] = {ra.x, ra.y, ra.z, ra.w};
            float b4[4] = {rb.x, rb.y, rb.z, rb.w};
#pragma unroll
            for (int i = 0; i < 4; i++)
#pragma unroll
                for (int j = 0; j < 4; j++)
                    acc[i][j] = fmaf(a4[i], b4[j], acc[i][j]);
        }
        __syncthreads();
    }
#pragma unroll
    for (int i = 0; i < 4; i++) {
        int r = row0 + ty * 4 + i;
        *reinterpret_cast<float4*>(C + (size_t)r * N + col0 + tx * 4) =
            make_float4(acc[i][0], acc[i][1], acc[i][2], acc[i][3]);
    }
}

// ---------------------------------------------------------------------------
// Main 128x128x16 SGEMM, double-buffered smem (one barrier per K-tile),
// padded smem rows (132) to reduce A-transpose STS conflicts.
// mode 0: plain.  mode 1: skip whole row-block if its batch is focus.
// mode 2: focus row-blocks use (A2, B2) instead of (A, B).
// A row stride == K, B/C row stride == N (holds for all call sites here).
// ---------------------------------------------------------------------------
__global__ __launch_bounds__(256, 2) void sgemm_db(
    const float* __restrict__ A, const float* __restrict__ B,
    const float* __restrict__ A2, const float* __restrict__ B2,
    float* __restrict__ C, int N, int K, int mode)
{
    constexpr int BM = 128, BN = 128, BK = 16, LDT = 132;
    __shared__ float As[2][BK][LDT];
    __shared__ float Bs[2][BK][LDT];

    const int row0 = blockIdx.y * BM;
    if (mode != 0) {
        const int focus = g_focus[row0 >> 14];   // 16384 rows per batch
        if (focus) {
            if (mode == 1) return;
            A = A2; B = B2;
        }
    }

    const int tid = threadIdx.x;
    const int tx = tid & 15, ty = tid >> 4;
    const int col0 = blockIdx.x * BN;

    const int a_r = tid >> 2;          // 0..63 (+0, +64)
    const int a_c = (tid & 3) << 2;    // 0,4,8,12
    const int b_r = tid >> 5;          // 0..7  (+0, +8)
    const int b_c = (tid & 31) << 2;   // 0..124

    const float* Ag = A + (size_t)row0 * K;
    const float* Bg = B + col0;

    float acc[8][8];
#pragma unroll
    for (int i = 0; i < 8; i++)
#pragma unroll
        for (int j = 0; j < 8; j++) acc[i][j] = 0.f;

    float4 pa[2], pb[2];
#pragma unroll
    for (int i = 0; i < 2; i++)
        pa[i] = *reinterpret_cast<const float4*>(Ag + (size_t)(a_r + i * 64) * K + a_c);
#pragma unroll
    for (int i = 0; i < 2; i++)
        pb[i] = *reinterpret_cast<const float4*>(Bg + (size_t)(b_r + i * 8) * N + b_c);

#pragma unroll
    for (int i = 0; i < 2; i++) {
        int r = a_r + i * 64;
        As[0][a_c + 0][r] = pa[i].x; As[0][a_c + 1][r] = pa[i].y;
        As[0][a_c + 2][r] = pa[i].z; As[0][a_c + 3][r] = pa[i].w;
    }
#pragma unroll
    for (int i = 0; i < 2; i++)
        *reinterpret_cast<float4*>(&Bs[0][b_r + i * 8][b_c]) = pb[i];
    __syncthreads();

    const int nt = K / BK;
    int cur = 0;
    for (int t = 0; t < nt; t++) {
        if (t + 1 < nt) {                 // issue next tile's LDGs before the FFMA block
            int k0 = (t + 1) * BK;
#pragma unroll
            for (int i = 0; i < 2; i++)
                pa[i] = *reinterpret_cast<const float4*>(Ag + (size_t)(a_r + i * 64) * K + k0 + a_c);
#pragma unroll
            for (int i = 0; i < 2; i++)
                pb[i] = *reinterpret_cast<const float4*>(Bg + (size_t)(k0 + b_r + i * 8) * N + b_c);
        }
#pragma unroll
        for (int kk = 0; kk < BK; kk++) {
            float ra[8], rb[8];
            *reinterpret_cast<float4*>(&ra[0]) = *reinterpret_cast<const float4*>(&As[cur][kk][ty * 4]);
            *reinterpret_cast<float4*>(&ra[4]) = *reinterpret_cast<const float4*>(&As[cur][kk][64 + ty * 4]);
            *reinterpret_cast<float4*>(&rb[0]) = *reinterpret_cast<const float4*>(&Bs[cur][kk][tx * 4]);
            *reinterpret_cast<float4*>(&rb[4]) = *reinterpret_cast<const float4*>(&Bs[cur][kk][64 + tx * 4]);
#pragma unroll
            for (int i = 0; i < 8; i++)
#pragma unroll
                for (int j = 0; j < 8; j++)
                    acc[i][j] = fmaf(ra[i], rb[j], acc[i][j]);
        }
        if (t + 1 < nt) {
            int nxt = cur ^ 1;
#pragma unroll
            for (int i = 0; i < 2; i++) {
                int r = a_r + i * 64;
                As[nxt][a_c + 0][r] = pa[i].x; As[nxt][a_c + 1][r] = pa[i].y;
                As[nxt][a_c + 2][r] = pa[i].z; As[nxt][a_c + 3][r] = pa[i].w;
            }
#pragma unroll
            for (int i = 0; i < 2; i++)
                *reinterpret_cast<float4*>(&Bs[nxt][b_r + i * 8][b_c]) = pb[i];
            __syncthreads();
            cur = nxt;
        }
    }

#pragma unroll
    for (int ig = 0; ig < 2; ig++)
#pragma unroll
        for (int i = 0; i < 4; i++) {
            int r = row0 + ig * 64 + ty * 4 + i;
#pragma unroll
            for (int jg = 0; jg < 2; jg++) {
                int c = col0 + jg * 64 + tx * 4;
                *reinterpret_cast<float4*>(C + (size_t)r * N + c) =
                    make_float4(acc[ig * 4 + i][jg * 4 + 0], acc[ig * 4 + i][jg * 4 + 1],
                                acc[ig * 4 + i][jg * 4 + 2], acc[ig * 4 + i][jg * 4 + 3]);
            }
        }
}

// ---------------------------------------------------------------------------
// Fused rotary + scale + sim + bias + softmax + AV. One block per (b,s,h).
// Focus batches are handled entirely by the composed-weight GEMM; skip them.
// ---------------------------------------------------------------------------
__global__ __launch_bounds__(256) void attn_kernel(const float* __restrict__ pos_bias)
{
    const int bs = blockIdx.x >> 3;     // b*S + s
    const int h  = blockIdx.x & 7;
    const int b  = bs / S_LEN;
    if (g_focus[b]) return;             // out = x @ Wcomb computed elsewhere

    const int t  = threadIdx.x;
    const int n  = t >> 4;
    const int dg = t & 15;
    const int d  = dg << 2;

    __shared__ float qs[16][68];
    __shared__ float ks[16][68];
    __shared__ float vs[16][68];
    __shared__ float sim[16][17];

    const int m = bs * NTOK + n;
    const float* row = g_qkv + (size_t)m * QKV_COLS + h * HDIM + d;
    float4 q4 = *reinterpret_cast<const float4*>(row);
    float4 k4 = *reinterpret_cast<const float4*>(row + 512);
    float4 v4 = *reinterpret_cast<const float4*>(row + 1024);

    // rotary: pairs (d,d+1) angle p0=d/2, (d+2,d+3) angle p1=d/2+1
    const float L2T = 0.41524101186092029f;   // log2(10000)/32
    float a0 = (float)n * exp2f(-(float)(d >> 1) * L2T);
    float a1 = (float)n * exp2f(-(float)((d >> 1) + 1) * L2T);
    float c0, s0, c1, s1;
    sincosf(a0, &s0, &c0);
    sincosf(a1, &s1, &c1);

    q4.x *= 0.125f; q4.y *= 0.125f; q4.z *= 0.125f; q4.w *= 0.125f;  // hd^-0.5

    float qx = q4.x * c0 - q4.y * s0, qy = q4.y * c0 + q4.x * s0;
    float qz = q4.z * c1 - q4.w * s1, qw = q4.w * c1 + q4.z * s1;
    float kx = k4.x * c0 - k4.y * s0, ky = k4.y * c0 + k4.x * s0;
    float kz = k4.z * c1 - k4.w * s1, kw = k4.w * c1 + k4.z * s1;

    *reinterpret_cast<float4*>(&qs[n][d]) = make_float4(qx, qy, qz, qw);
    *reinterpret_cast<float4*>(&ks[n][d]) = make_float4(kx, ky, kz, kw);
    *reinterpret_cast<float4*>(&vs[n][d]) = v4;
    __syncthreads();

    // sim[i][j] = q_i . k_j + pos_bias[h,i,j]
    {
        const float4* qr = reinterpret_cast<const float4*>(&qs[n][0]);
        const float4* kr = reinterpret_cast<const float4*>(&ks[dg][0]);
        float acc = 0.f;
#pragma unroll
        for (int dd = 0; dd < 16; dd++) {
            float4 a = qr[dd], bb = kr[dd];
            acc += a.x * bb.x + a.y * bb.y + a.z * bb.z + a.w * bb.w;
        }
        sim[n][dg] = acc + pos_bias[(h * 16 + n) * 16 + dg];
    }
    __syncthreads();

    if (t < 16) {
        float mx = -FLT_MAX;
#pragma unroll
        for (int j = 0; j < 16; j++) mx = fmaxf(mx, sim[t][j]);
        float e[16], sum = 0.f;
#pragma unroll
        for (int j = 0; j < 16; j++) { e[j] = expf(sim[t][j] - mx); sum += e[j]; }
#pragma unroll
        for (int j = 0; j < 16; j++) sim[t][j] = e[j] / sum;
    }
    __syncthreads();

    float4 o = make_float4(0.f, 0.f, 0.f, 0.f);
#pragma unroll
    for (int j = 0; j < 16; j++) {
        float a = sim[n][j];
        float4 vv = *reinterpret_cast<const float4*>(&vs[j][d]);
        o.x = fmaf(a, vv.x, o.x); o.y = fmaf(a, vv.y, o.y);
        o.z = fmaf(a, vv.z, o.z); o.w = fmaf(a, vv.w, o.w);
    }
    *reinterpret_cast<float4*>(g_ctx + (size_t)m * DMODEL + h * HDIM + d) = o;
}

// ---------------------------------------------------------------------------
extern "C" void kernel_launch(void* const* d_in, const int* in_sizes, int n_in,
                              void* d_out, int out_size)
{
    const float* x     = (const float*)d_in[0];   // (4,1024,16,512)
    const float* pbias = (const float*)d_in[1];   // (8,16,16)
    const float* Wqkv  = (const float*)d_in[2];   // (512,1536)
    const float* Wout  = (const float*)d_in[3];   // (512,512)
    const unsigned char* fmask = (const unsigned char*)d_in[4];
    float* out = (float*)d_out;                   // (4,1024,16,512)

    float *qkv = nullptr, *ctx = nullptr, *wcomb = nullptr;
    cudaGetSymbolAddress((void**)&qkv, g_qkv);
    cudaGetSymbolAddress((void**)&ctx, g_ctx);
    cudaGetSymbolAddress((void**)&wcomb, g_wcomb);

    dim3 blk(256);

    // 0) decode focus mask
    decode_mask<<<1, 1>>>(fmask);

    // 1) Wcomb = Wqkv[:,1024:1536] @ Wout   (512x512x512, one wave of 64 blocks)
    sgemm64<<<dim3(8, 8), blk>>>(Wqkv + 1024, QKV_COLS, Wout, wcomb, DMODEL, DMODEL);

    // 2) qkv = x @ W_qkv, skipping focus row-blocks entirely (mode 1)
    sgemm_db<<<dim3(QKV_COLS / 128, M_ROWS / 128), blk>>>(
        x, Wqkv, nullptr, nullptr, qkv, QKV_COLS, DMODEL, 1);

    // 3) fused attention -> g_ctx (non-focus rows only)
    attn_kernel<<<B_SZ * S_LEN * NH, blk>>>(pbias);

    // 4) out: non-focus = ctx @ Wout, focus = x @ Wcomb (mode 2)
    sgemm_db<<<dim3(DMODEL / 128, M_ROWS / 128), blk>>>(
        ctx, Wout, x, wcomb, out, DMODEL, DMODEL, 2);
}

// round 16
// speedup vs baseline: 1.6372x; 1.6372x over previous
#include <cuda_runtime.h>
#include <cuda_bf16.h>
#include <cstdint>
#include <cfloat>

// Problem constants
#define B_SZ   4
#define S_LEN  1024
#define NTOK   16
#define DMODEL 512
#define NH     8
#define HDIM   64
#define M_ROWS (B_SZ * S_LEN * NTOK)   // 65536
#define QKV_COLS (3 * NH * HDIM)       // 1536

// Scratch (allocation-free rule: __device__ globals)
__device__ float g_qkv[(size_t)M_ROWS * QKV_COLS];     // fp32, non-focus rows only
__device__ float g_wcomb[DMODEL * DMODEL];
__device__ __nv_bfloat16 g_xh[(size_t)M_ROWS * DMODEL];   // x split
__device__ __nv_bfloat16 g_xl[(size_t)M_ROWS * DMODEL];
__device__ __nv_bfloat16 g_ch[(size_t)M_ROWS * DMODEL];   // ctx split (attn writes)
__device__ __nv_bfloat16 g_cl[(size_t)M_ROWS * DMODEL];
__device__ __nv_bfloat16 g_wqh[QKV_COLS * DMODEL], g_wql[QKV_COLS * DMODEL];  // Wqkv^T
__device__ __nv_bfloat16 g_woh[DMODEL * DMODEL],  g_wol[DMODEL * DMODEL];     // Wout^T
__device__ __nv_bfloat16 g_wch[DMODEL * DMODEL],  g_wcl[DMODEL * DMODEL];     // Wcomb^T
__device__ int g_focus[B_SZ];

// ---------------------------------------------------------------------------
// PTX helpers (all baseline sm_80+ features — no 'a'-target required)
// ---------------------------------------------------------------------------
__device__ __forceinline__ uint32_t smem_u32(const void* p) {
    uint32_t a;
    asm("{ .reg .u64 t; cvta.to.shared.u64 t, %1; cvt.u32.u64 %0, t; }" : "=r"(a) : "l"(p));
    return a;
}
#define CPA16(dst, src) \
    asm volatile("cp.async.cg.shared.global [%0], [%1], 16;" :: "r"(dst), "l"(src))
#define CPCOMMIT() asm volatile("cp.async.commit_group;")
#define CPWAIT(n)  asm volatile("cp.async.wait_group %0;" :: "n"(n))
#define LDSM4(r, a) \
    asm volatile("ldmatrix.sync.aligned.m8n8.x4.shared.b16 {%0,%1,%2,%3}, [%4];" \
        : "=r"((r)[0]), "=r"((r)[1]), "=r"((r)[2]), "=r"((r)[3]) : "r"(a))
#define MMA_BF16(ac, af, bf) \
    asm volatile("mma.sync.aligned.m16n8k16.row.col.f32.bf16.bf16.f32 " \
        "{%0,%1,%2,%3}, {%4,%5,%6,%7}, {%8,%9}, {%0,%1,%2,%3};" \
        : "+f"((ac)[0]), "+f"((ac)[1]), "+f"((ac)[2]), "+f"((ac)[3]) \
        : "r"((af)[0]), "r"((af)[1]), "r"((af)[2]), "r"((af)[3]), \
          "r"((bf)[0]), "r"((bf)[1]))

// ---------------------------------------------------------------------------
// Mask decode (bool may arrive as u8 / i32 / f32) -> g_focus
// ---------------------------------------------------------------------------
__global__ void decode_mask(const unsigned char* __restrict__ fmask)
{
    const uint32_t* fw = reinterpret_cast<const uint32_t*>(fmask);
    uint32_t w[4] = {fw[0], fw[1], fw[2], fw[3]};
    bool is_f32 = true, is_i32 = true;
#pragma unroll
    for (int i = 0; i < 4; i++) {
        is_f32 &= (w[i] == 0u || w[i] == 0x3F800000u);
        is_i32 &= (w[i] <= 1u);
    }
#pragma unroll
    for (int b = 0; b < 4; b++)
        g_focus[b] = (is_f32 || is_i32) ? (w[b] != 0u) : (fmask[b] != 0);
}

// ---------------------------------------------------------------------------
// 64x64x16 fp32 SGEMM for Wcomb = Wqkv[:,1024:] @ Wout (512^3, one wave)
// ---------------------------------------------------------------------------
__global__ __launch_bounds__(256) void sgemm64(
    const float* __restrict__ A, int lda, const float* __restrict__ B,
    float* __restrict__ C, int N, int K)
{
    constexpr int BK = 16;
    __shared__ float As[BK][68];
    __shared__ float Bs[BK][68];
    const int tid = threadIdx.x;
    const int tx = tid & 15, ty = tid >> 4;
    const int row0 = blockIdx.y * 64, col0 = blockIdx.x * 64;
    const int a_r = tid >> 2, a_c = (tid & 3) << 2;
    const int b_r = tid >> 4, b_c = (tid & 15) << 2;

    float acc[4][4];
#pragma unroll
    for (int i = 0; i < 4; i++)
#pragma unroll
        for (int j = 0; j < 4; j++) acc[i][j] = 0.f;

    for (int k0 = 0; k0 < K; k0 += BK) {
        float4 va = *reinterpret_cast<const float4*>(A + (size_t)(row0 + a_r) * lda + k0 + a_c);
        As[a_c + 0][a_r] = va.x; As[a_c + 1][a_r] = va.y;
        As[a_c + 2][a_r] = va.z; As[a_c + 3][a_r] = va.w;
        *reinterpret_cast<float4*>(&Bs[b_r][b_c]) =
            *reinterpret_cast<const float4*>(B + (size_t)(k0 + b_r) * N + col0 + b_c);
        __syncthreads();
#pragma unroll
        for (int kk = 0; kk < BK; kk++) {
            float4 ra = *reinterpret_cast<const float4*>(&As[kk][ty * 4]);
            float4 rb = *reinterpret_cast<const float4*>(&Bs[kk][tx * 4]);
            float a4[4] = {ra.x, ra.y, ra.z, ra.w};
            float b4[4] = {rb.x, rb.y, rb.z, rb.w};
#pragma unroll
            for (int i = 0; i < 4; i++)
#pragma unroll
                for (int j = 0; j < 4; j++)
                    acc[i][j] = fmaf(a4[i], b4[j], acc[i][j]);
        }
        __syncthreads();
    }
#pragma unroll
    for (int i = 0; i < 4; i++)
        *reinterpret_cast<float4*>(C + (size_t)(row0 + ty * 4 + i) * N + col0 + tx * 4) =
            make_float4(acc[i][0], acc[i][1], acc[i][2], acc[i][3]);
}

// ---------------------------------------------------------------------------
// Transpose + bf16 hi/lo split: W[K][N] fp32 -> oh/ol [N][K] bf16
// ---------------------------------------------------------------------------
__global__ __launch_bounds__(256) void transpose_split_bf16(
    const float* __restrict__ W, int K, int N,
    __nv_bfloat16* __restrict__ oh, __nv_bfloat16* __restrict__ ol)
{
    __shared__ float s[32][33];
    const int k0 = blockIdx.y * 32, n0 = blockIdx.x * 32;
    const int tx = threadIdx.x & 31, ty = threadIdx.x >> 5;
#pragma unroll
    for (int i = 0; i < 4; i++)
        s[ty + i * 8][tx] = W[(size_t)(k0 + ty + i * 8) * N + n0 + tx];
    __syncthreads();
#pragma unroll
    for (int i = 0; i < 4; i++) {
        float v = s[tx][ty + i * 8];
        __nv_bfloat16 hv = __float2bfloat16(v);
        __nv_bfloat16 lv = __float2bfloat16(v - __bfloat162float(hv));
        size_t o = (size_t)(n0 + ty + i * 8) * K + k0 + tx;
        oh[o] = hv; ol[o] = lv;
    }
}

// ---------------------------------------------------------------------------
// Elementwise fp32 -> bf16 hi/lo split (for x), float4-vectorized
// ---------------------------------------------------------------------------
__global__ __launch_bounds__(256) void split_f32_bf16(
    const float4* __restrict__ in,
    __nv_bfloat162* __restrict__ oh, __nv_bfloat162* __restrict__ ol, int n4)
{
    int i = blockIdx.x * 256 + threadIdx.x;
    if (i >= n4) return;
    float4 v = in[i];
    __nv_bfloat16 h0 = __float2bfloat16(v.x), h1 = __float2bfloat16(v.y);
    __nv_bfloat16 h2 = __float2bfloat16(v.z), h3 = __float2bfloat16(v.w);
    __nv_bfloat16 l0 = __float2bfloat16(v.x - __bfloat162float(h0));
    __nv_bfloat16 l1 = __float2bfloat16(v.y - __bfloat162float(h1));
    __nv_bfloat16 l2 = __float2bfloat16(v.z - __bfloat162float(h2));
    __nv_bfloat16 l3 = __float2bfloat16(v.w - __bfloat162float(h3));
    __nv_bfloat162 a, b;
    a.x = h0; a.y = h1; b.x = h2; b.y = h3;
    oh[i * 2] = a; oh[i * 2 + 1] = b;
    a.x = l0; a.y = l1; b.x = l2; b.y = l3;
    ol[i * 2] = a; ol[i * 2 + 1] = b;
}

// ---------------------------------------------------------------------------
// bf16x3 emulated-fp32 GEMM on legacy tensor cores (mma.sync m16n8k16).
// C[M,N] = A[M,512] @ Bt[N,512]^T, A/B pre-split hi/lo bf16, fp32 accum.
// 128x128 CTA tile, BK=32, 2-stage cp.async pipeline, 8 warps (64x32 each).
// SMEM stage: A_hi | A_lo | B_hi | B_lo, each 128 rows x 32 halves, pitch 80B.
// mode 1: skip focus row-blocks. mode 2: focus row-blocks use A2/B2.
// ---------------------------------------------------------------------------
#define ST_AH 0
#define ST_AL 10240
#define ST_BH 20480
#define ST_BL 30720
#define ST_SZ 40960

__device__ __forceinline__ void load_stage(
    uint32_t sbase,
    const __nv_bfloat16* __restrict__ Ah, const __nv_bfloat16* __restrict__ Al,
    const __nv_bfloat16* __restrict__ Bh, const __nv_bfloat16* __restrict__ Bl,
    int k0, int tid)
{
#pragma unroll
    for (int c = 0; c < 2; c++) {
        int chunk = tid * 2 + c;                 // 512 chunks per array
        int row = chunk >> 2;
        int c16 = (chunk & 3) << 3;              // halves offset within row
        uint32_t so = (uint32_t)row * 80 + c16 * 2;
        size_t go = (size_t)row * 512 + k0 + c16;
        CPA16(sbase + ST_AH + so, Ah + go);
        CPA16(sbase + ST_AL + so, Al + go);
        CPA16(sbase + ST_BH + so, Bh + go);
        CPA16(sbase + ST_BL + so, Bl + go);
    }
}

__global__ __launch_bounds__(256, 2) void bgemm(
    const __nv_bfloat16* __restrict__ Ah, const __nv_bfloat16* __restrict__ Al,
    const __nv_bfloat16* __restrict__ Bth, const __nv_bfloat16* __restrict__ Btl,
    const __nv_bfloat16* __restrict__ A2h, const __nv_bfloat16* __restrict__ A2l,
    const __nv_bfloat16* __restrict__ B2h, const __nv_bfloat16* __restrict__ B2l,
    float* __restrict__ C, int N, int mode)
{
    const int row0 = blockIdx.y * 128;
    const int col0 = blockIdx.x * 128;
    if (mode != 0) {
        if (g_focus[row0 >> 14]) {               // 16384 rows per batch
            if (mode == 1) return;
            Ah = A2h; Al = A2l; Bth = B2h; Btl = B2l;
        }
    }
    extern __shared__ char smem[];
    const uint32_t sb = smem_u32(smem);
    const int tid = threadIdx.x;
    const int lane = tid & 31;
    const int wid = tid >> 5;
    const int wm = wid >> 2;                     // 0..1 (M 64-row half)
    const int wn = wid & 3;                      // 0..3 (N 32-col quarter)

    Ah  += (size_t)row0 * 512;  Al  += (size_t)row0 * 512;
    Bth += (size_t)col0 * 512;  Btl += (size_t)col0 * 512;

    float acc[4][4][4];
#pragma unroll
    for (int i = 0; i < 4; i++)
#pragma unroll
        for (int j = 0; j < 4; j++)
#pragma unroll
            for (int r = 0; r < 4; r++) acc[i][j][r] = 0.f;

    // prefetch stage 0
    load_stage(sb, Ah, Al, Bth, Btl, 0, tid);
    CPCOMMIT();

    // ldmatrix lane address bases (pitch 80 B; lanes 16-31 handle k+8 halves)
    const uint32_t lrow = (uint32_t)(lane & 15);
    const uint32_t lk   = (uint32_t)(lane >> 4) << 4;   // +16 bytes for k8..15
    const uint32_t aBase = sb + (wm * 64 + lrow) * 80 + lk;
    const uint32_t bBase = sb + (wn * 32 + lrow) * 80 + lk;

    for (int t = 0; t < 16; t++) {
        if (t < 15) {
            load_stage(sb + (uint32_t)((t + 1) & 1) * ST_SZ, Ah, Al, Bth, Btl,
                       (t + 1) * 32, tid);
            CPCOMMIT();
            CPWAIT(1);
        } else {
            CPWAIT(0);
        }
        __syncthreads();
        const uint32_t stage = (uint32_t)(t & 1) * ST_SZ;
#pragma unroll
        for (int kk = 0; kk < 2; kk++) {
            const uint32_t koff = stage + kk * 32;      // +16 halves = 32 bytes
            uint32_t af[4][4], bh[4][2], bl[4][2];
#pragma unroll
            for (int i = 0; i < 4; i++)
                LDSM4(af[i], aBase + ST_AH + koff + i * 1280);
            {
                uint32_t tmp[4];
#pragma unroll
                for (int p = 0; p < 2; p++) {
                    LDSM4(tmp, bBase + ST_BH + koff + p * 1280);
                    bh[p * 2][0] = tmp[0]; bh[p * 2][1] = tmp[2];
                    bh[p * 2 + 1][0] = tmp[1]; bh[p * 2 + 1][1] = tmp[3];
                    LDSM4(tmp, bBase + ST_BL + koff + p * 1280);
                    bl[p * 2][0] = tmp[0]; bl[p * 2][1] = tmp[2];
                    bl[p * 2 + 1][0] = tmp[1]; bl[p * 2 + 1][1] = tmp[3];
                }
            }
#pragma unroll
            for (int i = 0; i < 4; i++)
#pragma unroll
                for (int j = 0; j < 4; j++)
                    MMA_BF16(acc[i][j], af[i], bh[j]);      // hi·hi
#pragma unroll
            for (int i = 0; i < 4; i++)
#pragma unroll
                for (int j = 0; j < 4; j++)
                    MMA_BF16(acc[i][j], af[i], bl[j]);      // hi·lo
#pragma unroll
            for (int i = 0; i < 4; i++)
                LDSM4(af[i], aBase + ST_AL + koff + i * 1280);
#pragma unroll
            for (int i = 0; i < 4; i++)
#pragma unroll
                for (int j = 0; j < 4; j++)
                    MMA_BF16(acc[i][j], af[i], bh[j]);      // lo·hi
        }
        __syncthreads();
    }

    // epilogue: c0,c1 -> (row g, col t2*2..+1); c2,c3 -> row g+8
    const int g = lane >> 2, t4 = lane & 3;
#pragma unroll
    for (int i = 0; i < 4; i++) {
        const int r = row0 + wm * 64 + i * 16 + g;
#pragma unroll
        for (int j = 0; j < 4; j++) {
            const int c = col0 + wn * 32 + j * 8 + t4 * 2;
            *reinterpret_cast<float2*>(C + (size_t)r * N + c) =
                make_float2(acc[i][j][0], acc[i][j][1]);
            *reinterpret_cast<float2*>(C + (size_t)(r + 8) * N + c) =
                make_float2(acc[i][j][2], acc[i][j][3]);
        }
    }
}

// ---------------------------------------------------------------------------
// Fused rotary + scale + sim + bias + softmax + AV. One block per (b,s,h).
// Writes ctx directly as bf16 hi/lo split. Focus batches skipped (Wcomb path).
// ---------------------------------------------------------------------------
__global__ __launch_bounds__(256) void attn_kernel(const float* __restrict__ pos_bias)
{
    const int bs = blockIdx.x >> 3;
    const int hh = blockIdx.x & 7;
    const int b  = bs / S_LEN;
    if (g_focus[b]) return;

    const int t  = threadIdx.x;
    const int n  = t >> 4;
    const int dg = t & 15;
    const int d  = dg << 2;

    __shared__ float qs[16][68];
    __shared__ float ks[16][68];
    __shared__ float vs[16][68];
    __shared__ float sim[16][17];

    const int m = bs * NTOK + n;
    const float* row = g_qkv + (size_t)m * QKV_COLS + hh * HDIM + d;
    float4 q4 = *reinterpret_cast<const float4*>(row);
    float4 k4 = *reinterpret_cast<const float4*>(row + 512);
    float4 v4 = *reinterpret_cast<const float4*>(row + 1024);

    const float L2T = 0.41524101186092029f;   // log2(10000)/32
    float a0 = (float)n * exp2f(-(float)(d >> 1) * L2T);
    float a1 = (float)n * exp2f(-(float)((d >> 1) + 1) * L2T);
    float c0, s0, c1, s1;
    sincosf(a0, &s0, &c0);
    sincosf(a1, &s1, &c1);

    q4.x *= 0.125f; q4.y *= 0.125f; q4.z *= 0.125f; q4.w *= 0.125f;

    float qx = q4.x * c0 - q4.y * s0, qy = q4.y * c0 + q4.x * s0;
    float qz = q4.z * c1 - q4.w * s1, qw = q4.w * c1 + q4.z * s1;
    float kx = k4.x * c0 - k4.y * s0, ky = k4.y * c0 + k4.x * s0;
    float kz = k4.z * c1 - k4.w * s1, kw = k4.w * c1 + k4.z * s1;

    *reinterpret_cast<float4*>(&qs[n][d]) = make_float4(qx, qy, qz, qw);
    *reinterpret_cast<float4*>(&ks[n][d]) = make_float4(kx, ky, kz, kw);
    *reinterpret_cast<float4*>(&vs[n][d]) = v4;
    __syncthreads();

    {
        const float4* qr = reinterpret_cast<const float4*>(&qs[n][0]);
        const float4* kr = reinterpret_cast<const float4*>(&ks[dg][0]);
        float acc = 0.f;
#pragma unroll
        for (int dd = 0; dd < 16; dd++) {
            float4 a = qr[dd], bb = kr[dd];
            acc += a.x * bb.x + a.y * bb.y + a.z * bb.z + a.w * bb.w;
        }
        sim[n][dg] = acc + pos_bias[(hh * 16 + n) * 16 + dg];
    }
    __syncthreads();

    if (t < 16) {
        float mx = -FLT_MAX;
#pragma unroll
        for (int j = 0; j < 16; j++) mx = fmaxf(mx, sim[t][j]);
        float e[16], sum = 0.f;
#pragma unroll
        for (int j = 0; j < 16; j++) { e[j] = expf(sim[t][j] - mx); sum += e[j]; }
#pragma unroll
        for (int j = 0; j < 16; j++) sim[t][j] = e[j] / sum;
    }
    __syncthreads();

    float4 o = make_float4(0.f, 0.f, 0.f, 0.f);
#pragma unroll
    for (int j = 0; j < 16; j++) {
        float a = sim[n][j];
        float4 vv = *reinterpret_cast<const float4*>(&vs[j][d]);
        o.x = fmaf(a, vv.x, o.x); o.y = fmaf(a, vv.y, o.y);
        o.z = fmaf(a, vv.z, o.z); o.w = fmaf(a, vv.w, o.w);
    }

    // bf16 hi/lo split written directly (feeds the output GEMM)
    const size_t off = (size_t)m * DMODEL + hh * HDIM + d;
    __nv_bfloat16 h0 = __float2bfloat16(o.x), h1 = __float2bfloat16(o.y);
    __nv_bfloat16 h2 = __float2bfloat16(o.z), h3 = __float2bfloat16(o.w);
    __nv_bfloat162 p0, p1;
    p0.x = h0; p0.y = h1; p1.x = h2; p1.y = h3;
    *reinterpret_cast<__nv_bfloat162*>(&g_ch[off])     = p0;
    *reinterpret_cast<__nv_bfloat162*>(&g_ch[off + 2]) = p1;
    p0.x = __float2bfloat16(o.x - __bfloat162float(h0));
    p0.y = __float2bfloat16(o.y - __bfloat162float(h1));
    p1.x = __float2bfloat16(o.z - __bfloat162float(h2));
    p1.y = __float2bfloat16(o.w - __bfloat162float(h3));
    *reinterpret_cast<__nv_bfloat162*>(&g_cl[off])     = p0;
    *reinterpret_cast<__nv_bfloat162*>(&g_cl[off + 2]) = p1;
}

// ---------------------------------------------------------------------------
extern "C" void kernel_launch(void* const* d_in, const int* in_sizes, int n_in,
                              void* d_out, int out_size)
{
    const float* x     = (const float*)d_in[0];   // (4,1024,16,512)
    const float* pbias = (const float*)d_in[1];   // (8,16,16)
    const float* Wqkv  = (const float*)d_in[2];   // (512,1536)
    const float* Wout  = (const float*)d_in[3];   // (512,512)
    const unsigned char* fmask = (const unsigned char*)d_in[4];
    float* out = (float*)d_out;                   // (4,1024,16,512)

    float *qkv, *wcomb;
    __nv_bfloat16 *xh, *xl, *ch, *cl, *wqh, *wql, *woh, *wol, *wch, *wcl;
    cudaGetSymbolAddress((void**)&qkv,   g_qkv);
    cudaGetSymbolAddress((void**)&wcomb, g_wcomb);
    cudaGetSymbolAddress((void**)&xh,  g_xh);  cudaGetSymbolAddress((void**)&xl,  g_xl);
    cudaGetSymbolAddress((void**)&ch,  g_ch);  cudaGetSymbolAddress((void**)&cl,  g_cl);
    cudaGetSymbolAddress((void**)&wqh, g_wqh); cudaGetSymbolAddress((void**)&wql, g_wql);
    cudaGetSymbolAddress((void**)&woh, g_woh); cudaGetSymbolAddress((void**)&wol, g_wol);
    cudaGetSymbolAddress((void**)&wch, g_wch); cudaGetSymbolAddress((void**)&wcl, g_wcl);

    cudaFuncSetAttribute(bgemm, cudaFuncAttributeMaxDynamicSharedMemorySize, 2 * ST_SZ);
    const int SMEM_BYTES = 2 * ST_SZ;   // 81920
    dim3 blk(256);

    // 0) decode focus mask
    decode_mask<<<1, 1>>>(fmask);

    // 1) Wcomb = Wqkv[:,1024:1536] @ Wout (fp32, 512^3)
    sgemm64<<<dim3(8, 8), blk>>>(Wqkv + 1024, QKV_COLS, Wout, wcomb, DMODEL, DMODEL);

    // 2) transpose + bf16-split all weight operands -> [N][512]
    transpose_split_bf16<<<dim3(QKV_COLS / 32, DMODEL / 32), blk>>>(Wqkv, DMODEL, QKV_COLS, wqh, wql);
    transpose_split_bf16<<<dim3(DMODEL / 32, DMODEL / 32), blk>>>(Wout,  DMODEL, DMODEL, woh, wol);
    transpose_split_bf16<<<dim3(DMODEL / 32, DMODEL / 32), blk>>>(wcomb, DMODEL, DMODEL, wch, wcl);

    // 3) split x -> bf16 hi/lo
    split_f32_bf16<<<(M_ROWS * DMODEL / 4 + 255) / 256, blk>>>(
        (const float4*)x, (__nv_bfloat162*)xh, (__nv_bfloat162*)xl, M_ROWS * DMODEL / 4);

    // 4) qkv = x @ Wqkv (legacy tensor cores, bf16x3; skip focus row-blocks)
    bgemm<<<dim3(QKV_COLS / 128, M_ROWS / 128), blk, SMEM_BYTES>>>(
        xh, xl, wqh, wql, nullptr, nullptr, nullptr, nullptr, qkv, QKV_COLS, 1);

    // 5) fused attention -> ctx hi/lo (non-focus rows only)
    attn_kernel<<<B_SZ * S_LEN * NH, blk>>>(pbias);

    // 6) out: non-focus = ctx @ Wout, focus = x @ Wcomb (bf16x3)
    bgemm<<<dim3(DMODEL / 128, M_ROWS / 128), blk, SMEM_BYTES>>>(
        ch, cl, woh, wol, xh, xl, wch, wcl, out, DMODEL, 2);
}

// round 17
// speedup vs baseline: 1.6389x; 1.0011x over previous
#include <cuda_runtime.h>
#include <cuda_bf16.h>
#include <cstdint>
#include <cfloat>

// Problem constants
#define B_SZ   4
#define S_LEN  1024
#define NTOK   16
#define DMODEL 512
#define NH     8
#define HDIM   64
#define M_ROWS (B_SZ * S_LEN * NTOK)   // 65536
#define QKV_COLS (3 * NH * HDIM)       // 1536

// Scratch (allocation-free rule: __device__ globals)
__device__ float g_qkv[(size_t)M_ROWS * QKV_COLS];     // fp32, non-focus rows only
__device__ float g_wcomb[DMODEL * DMODEL];
__device__ __nv_bfloat16 g_xh[(size_t)M_ROWS * DMODEL];   // x split
__device__ __nv_bfloat16 g_xl[(size_t)M_ROWS * DMODEL];
__device__ __nv_bfloat16 g_ch[(size_t)M_ROWS * DMODEL];   // ctx split (attn writes)
__device__ __nv_bfloat16 g_cl[(size_t)M_ROWS * DMODEL];
__device__ __nv_bfloat16 g_wqh[QKV_COLS * DMODEL], g_wql[QKV_COLS * DMODEL];  // Wqkv^T
__device__ __nv_bfloat16 g_woh[DMODEL * DMODEL],  g_wol[DMODEL * DMODEL];     // Wout^T
__device__ __nv_bfloat16 g_wch[DMODEL * DMODEL],  g_wcl[DMODEL * DMODEL];     // Wcomb^T
__device__ int g_focus[B_SZ];

// ---------------------------------------------------------------------------
// PTX helpers (all baseline sm_80+ features — no 'a'-target required)
// ---------------------------------------------------------------------------
__device__ __forceinline__ uint32_t smem_u32(const void* p) {
    uint32_t a;
    asm("{ .reg .u64 t; cvta.to.shared.u64 t, %1; cvt.u32.u64 %0, t; }" : "=r"(a) : "l"(p));
    return a;
}
#define CPA16(dst, src) \
    asm volatile("cp.async.cg.shared.global [%0], [%1], 16;" :: "r"(dst), "l"(src))
#define CPCOMMIT() asm volatile("cp.async.commit_group;")
#define CPWAIT(n)  asm volatile("cp.async.wait_group %0;" :: "n"(n))
#define LDSM4(r, a) \
    asm volatile("ldmatrix.sync.aligned.m8n8.x4.shared.b16 {%0,%1,%2,%3}, [%4];" \
        : "=r"((r)[0]), "=r"((r)[1]), "=r"((r)[2]), "=r"((r)[3]) : "r"(a))
#define MMA_BF16(ac, af, bf) \
    asm volatile("mma.sync.aligned.m16n8k16.row.col.f32.bf16.bf16.f32 " \
        "{%0,%1,%2,%3}, {%4,%5,%6,%7}, {%8,%9}, {%0,%1,%2,%3};" \
        : "+f"((ac)[0]), "+f"((ac)[1]), "+f"((ac)[2]), "+f"((ac)[3]) \
        : "r"((af)[0]), "r"((af)[1]), "r"((af)[2]), "r"((af)[3]), \
          "r"((bf)[0]), "r"((bf)[1]))

// ---------------------------------------------------------------------------
// Mask decode (bool may arrive as u8 / i32 / f32) -> g_focus
// ---------------------------------------------------------------------------
__global__ void decode_mask(const unsigned char* __restrict__ fmask)
{
    const uint32_t* fw = reinterpret_cast<const uint32_t*>(fmask);
    uint32_t w[4] = {fw[0], fw[1], fw[2], fw[3]};
    bool is_f32 = true, is_i32 = true;
#pragma unroll
    for (int i = 0; i < 4; i++) {
        is_f32 &= (w[i] == 0u || w[i] == 0x3F800000u);
        is_i32 &= (w[i] <= 1u);
    }
#pragma unroll
    for (int b = 0; b < 4; b++)
        g_focus[b] = (is_f32 || is_i32) ? (w[b] != 0u) : (fmask[b] != 0);
}

// ---------------------------------------------------------------------------
// 64x64x16 fp32 SGEMM for Wcomb = Wqkv[:,1024:] @ Wout (512^3, one wave)
// ---------------------------------------------------------------------------
__global__ __launch_bounds__(256) void sgemm64(
    const float* __restrict__ A, int lda, const float* __restrict__ B,
    float* __restrict__ C, int N, int K)
{
    constexpr int BK = 16;
    __shared__ float As[BK][68];
    __shared__ float Bs[BK][68];
    const int tid = threadIdx.x;
    const int tx = tid & 15, ty = tid >> 4;
    const int row0 = blockIdx.y * 64, col0 = blockIdx.x * 64;
    const int a_r = tid >> 2, a_c = (tid & 3) << 2;
    const int b_r = tid >> 4, b_c = (tid & 15) << 2;

    float acc[4][4];
#pragma unroll
    for (int i = 0; i < 4; i++)
#pragma unroll
        for (int j = 0; j < 4; j++) acc[i][j] = 0.f;

    for (int k0 = 0; k0 < K; k0 += BK) {
        float4 va = *reinterpret_cast<const float4*>(A + (size_t)(row0 + a_r) * lda + k0 + a_c);
        As[a_c + 0][a_r] = va.x; As[a_c + 1][a_r] = va.y;
        As[a_c + 2][a_r] = va.z; As[a_c + 3][a_r] = va.w;
        *reinterpret_cast<float4*>(&Bs[b_r][b_c]) =
            *reinterpret_cast<const float4*>(B + (size_t)(k0 + b_r) * N + col0 + b_c);
        __syncthreads();
#pragma unroll
        for (int kk = 0; kk < BK; kk++) {
            float4 ra = *reinterpret_cast<const float4*>(&As[kk][ty * 4]);
            float4 rb = *reinterpret_cast<const float4*>(&Bs[kk][tx * 4]);
            float a4[4] = {ra.x, ra.y, ra.z, ra.w};
            float b4[4] = {rb.x, rb.y, rb.z, rb.w};
#pragma unroll
            for (int i = 0; i < 4; i++)
#pragma unroll
                for (int j = 0; j < 4; j++)
                    acc[i][j] = fmaf(a4[i], b4[j], acc[i][j]);
        }
        __syncthreads();
    }
#pragma unroll
    for (int i = 0; i < 4; i++)
        *reinterpret_cast<float4*>(C + (size_t)(row0 + ty * 4 + i) * N + col0 + tx * 4) =
            make_float4(acc[i][0], acc[i][1], acc[i][2], acc[i][3]);
}

// ---------------------------------------------------------------------------
// Transpose + bf16 hi/lo split: W[K][N] fp32 -> oh/ol [N][K] bf16
// ---------------------------------------------------------------------------
__global__ __launch_bounds__(256) void transpose_split_bf16(
    const float* __restrict__ W, int K, int N,
    __nv_bfloat16* __restrict__ oh, __nv_bfloat16* __restrict__ ol)
{
    __shared__ float s[32][33];
    const int k0 = blockIdx.y * 32, n0 = blockIdx.x * 32;
    const int tx = threadIdx.x & 31, ty = threadIdx.x >> 5;
#pragma unroll
    for (int i = 0; i < 4; i++)
        s[ty + i * 8][tx] = W[(size_t)(k0 + ty + i * 8) * N + n0 + tx];
    __syncthreads();
#pragma unroll
    for (int i = 0; i < 4; i++) {
        float v = s[tx][ty + i * 8];
        __nv_bfloat16 hv = __float2bfloat16(v);
        __nv_bfloat16 lv = __float2bfloat16(v - __bfloat162float(hv));
        size_t o = (size_t)(n0 + ty + i * 8) * K + k0 + tx;
        oh[o] = hv; ol[o] = lv;
    }
}

// ---------------------------------------------------------------------------
// Elementwise fp32 -> bf16 hi/lo split (for x), float4-vectorized
// ---------------------------------------------------------------------------
__global__ __launch_bounds__(256) void split_f32_bf16(
    const float4* __restrict__ in,
    __nv_bfloat162* __restrict__ oh, __nv_bfloat162* __restrict__ ol, int n4)
{
    int i = blockIdx.x * 256 + threadIdx.x;
    if (i >= n4) return;
    float4 v = in[i];
    __nv_bfloat16 h0 = __float2bfloat16(v.x), h1 = __float2bfloat16(v.y);
    __nv_bfloat16 h2 = __float2bfloat16(v.z), h3 = __float2bfloat16(v.w);
    __nv_bfloat16 l0 = __float2bfloat16(v.x - __bfloat162float(h0));
    __nv_bfloat16 l1 = __float2bfloat16(v.y - __bfloat162float(h1));
    __nv_bfloat16 l2 = __float2bfloat16(v.z - __bfloat162float(h2));
    __nv_bfloat16 l3 = __float2bfloat16(v.w - __bfloat162float(h3));
    __nv_bfloat162 a, b;
    a.x = h0; a.y = h1; b.x = h2; b.y = h3;
    oh[i * 2] = a; oh[i * 2 + 1] = b;
    a.x = l0; a.y = l1; b.x = l2; b.y = l3;
    ol[i * 2] = a; ol[i * 2 + 1] = b;
}

// ---------------------------------------------------------------------------
// bf16x3 emulated-fp32 GEMM on legacy tensor cores (mma.sync m16n8k16).
// C[M,N] = A[M,512] @ Bt[N,512]^T, A/B pre-split hi/lo bf16, fp32 accum.
// 128x128 CTA tile, BK=32, 2-stage cp.async pipeline, 8 warps (64x32 each).
// SMEM stage: A_hi | A_lo | B_hi | B_lo, each 128 rows x 32 halves, pitch 80B.
// mode 1: skip focus row-blocks. mode 2: focus row-blocks use A2/B2.
// ---------------------------------------------------------------------------
#define ST_AH 0
#define ST_AL 10240
#define ST_BH 20480
#define ST_BL 30720
#define ST_SZ 40960

__device__ __forceinline__ void load_stage(
    uint32_t sbase,
    const __nv_bfloat16* __restrict__ Ah, const __nv_bfloat16* __restrict__ Al,
    const __nv_bfloat16* __restrict__ Bh, const __nv_bfloat16* __restrict__ Bl,
    int k0, int tid)
{
#pragma unroll
    for (int c = 0; c < 2; c++) {
        int chunk = tid * 2 + c;                 // 512 chunks per array
        int row = chunk >> 2;
        int c16 = (chunk & 3) << 3;              // halves offset within row
        uint32_t so = (uint32_t)row * 80 + c16 * 2;
        size_t go = (size_t)row * 512 + k0 + c16;
        CPA16(sbase + ST_AH + so, Ah + go);
        CPA16(sbase + ST_AL + so, Al + go);
        CPA16(sbase + ST_BH + so, Bh + go);
        CPA16(sbase + ST_BL + so, Bl + go);
    }
}

__global__ __launch_bounds__(256, 2) void bgemm(
    const __nv_bfloat16* __restrict__ Ah, const __nv_bfloat16* __restrict__ Al,
    const __nv_bfloat16* __restrict__ Bth, const __nv_bfloat16* __restrict__ Btl,
    const __nv_bfloat16* __restrict__ A2h, const __nv_bfloat16* __restrict__ A2l,
    const __nv_bfloat16* __restrict__ B2h, const __nv_bfloat16* __restrict__ B2l,
    float* __restrict__ C, int N, int mode)
{
    const int row0 = blockIdx.y * 128;
    const int col0 = blockIdx.x * 128;
    if (mode != 0) {
        if (g_focus[row0 >> 14]) {               // 16384 rows per batch
            if (mode == 1) return;
            Ah = A2h; Al = A2l; Bth = B2h; Btl = B2l;
        }
    }
    extern __shared__ char smem[];
    const uint32_t sb = smem_u32(smem);
    const int tid = threadIdx.x;
    const int lane = tid & 31;
    const int wid = tid >> 5;
    const int wm = wid >> 2;                     // 0..1 (M 64-row half)
    const int wn = wid & 3;                      // 0..3 (N 32-col quarter)

    Ah  += (size_t)row0 * 512;  Al  += (size_t)row0 * 512;
    Bth += (size_t)col0 * 512;  Btl += (size_t)col0 * 512;

    float acc[4][4][4];
#pragma unroll
    for (int i = 0; i < 4; i++)
#pragma unroll
        for (int j = 0; j < 4; j++)
#pragma unroll
            for (int r = 0; r < 4; r++) acc[i][j][r] = 0.f;

    // prefetch stage 0
    load_stage(sb, Ah, Al, Bth, Btl, 0, tid);
    CPCOMMIT();

    // ldmatrix lane address bases (pitch 80 B; lanes 16-31 handle k+8 halves)
    const uint32_t lrow = (uint32_t)(lane & 15);
    const uint32_t lk   = (uint32_t)(lane >> 4) << 4;   // +16 bytes for k8..15
    const uint32_t aBase = sb + (wm * 64 + lrow) * 80 + lk;
    const uint32_t bBase = sb + (wn * 32 + lrow) * 80 + lk;

    for (int t = 0; t < 16; t++) {
        if (t < 15) {
            load_stage(sb + (uint32_t)((t + 1) & 1) * ST_SZ, Ah, Al, Bth, Btl,
                       (t + 1) * 32, tid);
            CPCOMMIT();
            CPWAIT(1);
        } else {
            CPWAIT(0);
        }
        __syncthreads();
        const uint32_t stage = (uint32_t)(t & 1) * ST_SZ;
#pragma unroll
        for (int kk = 0; kk < 2; kk++) {
            const uint32_t koff = stage + kk * 32;      // +16 halves = 32 bytes
            uint32_t af[4][4], bh[4][2], bl[4][2];
#pragma unroll
            for (int i = 0; i < 4; i++)
                LDSM4(af[i], aBase + ST_AH + koff + i * 1280);
            {
                uint32_t tmp[4];
#pragma unroll
                for (int p = 0; p < 2; p++) {
                    LDSM4(tmp, bBase + ST_BH + koff + p * 1280);
                    bh[p * 2][0] = tmp[0]; bh[p * 2][1] = tmp[2];
                    bh[p * 2 + 1][0] = tmp[1]; bh[p * 2 + 1][1] = tmp[3];
                    LDSM4(tmp, bBase + ST_BL + koff + p * 1280);
                    bl[p * 2][0] = tmp[0]; bl[p * 2][1] = tmp[2];
                    bl[p * 2 + 1][0] = tmp[1]; bl[p * 2 + 1][1] = tmp[3];
                }
            }
#pragma unroll
            for (int i = 0; i < 4; i++)
#pragma unroll
                for (int j = 0; j < 4; j++)
                    MMA_BF16(acc[i][j], af[i], bh[j]);      // hi·hi
#pragma unroll
            for (int i = 0; i < 4; i++)
#pragma unroll
                for (int j = 0; j < 4; j++)
                    MMA_BF16(acc[i][j], af[i], bl[j]);      // hi·lo
#pragma unroll
            for (int i = 0; i < 4; i++)
                LDSM4(af[i], aBase + ST_AL + koff + i * 1280);
#pragma unroll
            for (int i = 0; i < 4; i++)
#pragma unroll
                for (int j = 0; j < 4; j++)
                    MMA_BF16(acc[i][j], af[i], bh[j]);      // lo·hi
        }
        __syncthreads();
    }

    // epilogue: c0,c1 -> (row g, col t2*2..+1); c2,c3 -> row g+8
    const int g = lane >> 2, t4 = lane & 3;
#pragma unroll
    for (int i = 0; i < 4; i++) {
        const int r = row0 + wm * 64 + i * 16 + g;
#pragma unroll
        for (int j = 0; j < 4; j++) {
            const int c = col0 + wn * 32 + j * 8 + t4 * 2;
            *reinterpret_cast<float2*>(C + (size_t)r * N + c) =
                make_float2(acc[i][j][0], acc[i][j][1]);
            *reinterpret_cast<float2*>(C + (size_t)(r + 8) * N + c) =
                make_float2(acc[i][j][2], acc[i][j][3]);
        }
    }
}

// ---------------------------------------------------------------------------
// Fused rotary + scale + sim + bias + softmax + AV. One block per (b,s,h).
// Writes ctx directly as bf16 hi/lo split. Focus batches skipped (Wcomb path).
// ---------------------------------------------------------------------------
__global__ __launch_bounds__(256) void attn_kernel(const float* __restrict__ pos_bias)
{
    const int bs = blockIdx.x >> 3;
    const int hh = blockIdx.x & 7;
    const int b  = bs / S_LEN;
    if (g_focus[b]) return;

    const int t  = threadIdx.x;
    const int n  = t >> 4;
    const int dg = t & 15;
    const int d  = dg << 2;

    __shared__ float qs[16][68];
    __shared__ float ks[16][68];
    __shared__ float vs[16][68];
    __shared__ float sim[16][17];

    const int m = bs * NTOK + n;
    const float* row = g_qkv + (size_t)m * QKV_COLS + hh * HDIM + d;
    float4 q4 = *reinterpret_cast<const float4*>(row);
    float4 k4 = *reinterpret_cast<const float4*>(row + 512);
    float4 v4 = *reinterpret_cast<const float4*>(row + 1024);

    const float L2T = 0.41524101186092029f;   // log2(10000)/32
    float a0 = (float)n * exp2f(-(float)(d >> 1) * L2T);
    float a1 = (float)n * exp2f(-(float)((d >> 1) + 1) * L2T);
    float c0, s0, c1, s1;
    sincosf(a0, &s0, &c0);
    sincosf(a1, &s1, &c1);

    q4.x *= 0.125f; q4.y *= 0.125f; q4.z *= 0.125f; q4.w *= 0.125f;

    float qx = q4.x * c0 - q4.y * s0, qy = q4.y * c0 + q4.x * s0;
    float qz = q4.z * c1 - q4.w * s1, qw = q4.w * c1 + q4.z * s1;
    float kx = k4.x * c0 - k4.y * s0, ky = k4.y * c0 + k4.x * s0;
    float kz = k4.z * c1 - k4.w * s1, kw = k4.w * c1 + k4.z * s1;

    *reinterpret_cast<float4*>(&qs[n][d]) = make_float4(qx, qy, qz, qw);
    *reinterpret_cast<float4*>(&ks[n][d]) = make_float4(kx, ky, kz, kw);
    *reinterpret_cast<float4*>(&vs[n][d]) = v4;
    __syncthreads();

    {
        const float4* qr = reinterpret_cast<const float4*>(&qs[n][0]);
        const float4* kr = reinterpret_cast<const float4*>(&ks[dg][0]);
        float acc = 0.f;
#pragma unroll
        for (int dd = 0; dd < 16; dd++) {
            float4 a = qr[dd], bb = kr[dd];
            acc += a.x * bb.x + a.y * bb.y + a.z * bb.z + a.w * bb.w;
        }
        sim[n][dg] = acc + pos_bias[(hh * 16 + n) * 16 + dg];
    }
    __syncthreads();

    if (t < 16) {
        float mx = -FLT_MAX;
#pragma unroll
        for (int j = 0; j < 16; j++) mx = fmaxf(mx, sim[t][j]);
        float e[16], sum = 0.f;
#pragma unroll
        for (int j = 0; j < 16; j++) { e[j] = expf(sim[t][j] - mx); sum += e[j]; }
#pragma unroll
        for (int j = 0; j < 16; j++) sim[t][j] = e[j] / sum;
    }
    __syncthreads();

    float4 o = make_float4(0.f, 0.f, 0.f, 0.f);
#pragma unroll
    for (int j = 0; j < 16; j++) {
        float a = sim[n][j];
        float4 vv = *reinterpret_cast<const float4*>(&vs[j][d]);
        o.x = fmaf(a, vv.x, o.x); o.y = fmaf(a, vv.y, o.y);
        o.z = fmaf(a, vv.z, o.z); o.w = fmaf(a, vv.w, o.w);
    }

    // bf16 hi/lo split written directly (feeds the output GEMM)
    const size_t off = (size_t)m * DMODEL + hh * HDIM + d;
    __nv_bfloat16 h0 = __float2bfloat16(o.x), h1 = __float2bfloat16(o.y);
    __nv_bfloat16 h2 = __float2bfloat16(o.z), h3 = __float2bfloat16(o.w);
    __nv_bfloat162 p0, p1;
    p0.x = h0; p0.y = h1; p1.x = h2; p1.y = h3;
    *reinterpret_cast<__nv_bfloat162*>(&g_ch[off])     = p0;
    *reinterpret_cast<__nv_bfloat162*>(&g_ch[off + 2]) = p1;
    p0.x = __float2bfloat16(o.x - __bfloat162float(h0));
    p0.y = __float2bfloat16(o.y - __bfloat162float(h1));
    p1.x = __float2bfloat16(o.z - __bfloat162float(h2));
    p1.y = __float2bfloat16(o.w - __bfloat162float(h3));
    *reinterpret_cast<__nv_bfloat162*>(&g_cl[off])     = p0;
    *reinterpret_cast<__nv_bfloat162*>(&g_cl[off + 2]) = p1;
}

// ---------------------------------------------------------------------------
extern "C" void kernel_launch(void* const* d_in, const int* in_sizes, int n_in,
                              void* d_out, int out_size)
{
    const float* x     = (const float*)d_in[0];   // (4,1024,16,512)
    const float* pbias = (const float*)d_in[1];   // (8,16,16)
    const float* Wqkv  = (const float*)d_in[2];   // (512,1536)
    const float* Wout  = (const float*)d_in[3];   // (512,512)
    const unsigned char* fmask = (const unsigned char*)d_in[4];
    float* out = (float*)d_out;                   // (4,1024,16,512)

    float *qkv, *wcomb;
    __nv_bfloat16 *xh, *xl, *ch, *cl, *wqh, *wql, *woh, *wol, *wch, *wcl;
    cudaGetSymbolAddress((void**)&qkv,   g_qkv);
    cudaGetSymbolAddress((void**)&wcomb, g_wcomb);
    cudaGetSymbolAddress((void**)&xh,  g_xh);  cudaGetSymbolAddress((void**)&xl,  g_xl);
    cudaGetSymbolAddress((void**)&ch,  g_ch);  cudaGetSymbolAddress((void**)&cl,  g_cl);
    cudaGetSymbolAddress((void**)&wqh, g_wqh); cudaGetSymbolAddress((void**)&wql, g_wql);
    cudaGetSymbolAddress((void**)&woh, g_woh); cudaGetSymbolAddress((void**)&wol, g_wol);
    cudaGetSymbolAddress((void**)&wch, g_wch); cudaGetSymbolAddress((void**)&wcl, g_wcl);

    cudaFuncSetAttribute(bgemm, cudaFuncAttributeMaxDynamicSharedMemorySize, 2 * ST_SZ);
    const int SMEM_BYTES = 2 * ST_SZ;   // 81920
    dim3 blk(256);

    // 0) decode focus mask
    decode_mask<<<1, 1>>>(fmask);

    // 1) Wcomb = Wqkv[:,1024:1536] @ Wout (fp32, 512^3)
    sgemm64<<<dim3(8, 8), blk>>>(Wqkv + 1024, QKV_COLS, Wout, wcomb, DMODEL, DMODEL);

    // 2) transpose + bf16-split all weight operands -> [N][512]
    transpose_split_bf16<<<dim3(QKV_COLS / 32, DMODEL / 32), blk>>>(Wqkv, DMODEL, QKV_COLS, wqh, wql);
    transpose_split_bf16<<<dim3(DMODEL / 32, DMODEL / 32), blk>>>(Wout,  DMODEL, DMODEL, woh, wol);
    transpose_split_bf16<<<dim3(DMODEL / 32, DMODEL / 32), blk>>>(wcomb, DMODEL, DMODEL, wch, wcl);

    // 3) split x -> bf16 hi/lo
    split_f32_bf16<<<(M_ROWS * DMODEL / 4 + 255) / 256, blk>>>(
        (const float4*)x, (__nv_bfloat162*)xh, (__nv_bfloat162*)xl, M_ROWS * DMODEL / 4);

    // 4) qkv = x @ Wqkv (legacy tensor cores, bf16x3; skip focus row-blocks)
    bgemm<<<dim3(QKV_COLS / 128, M_ROWS / 128), blk, SMEM_BYTES>>>(
        xh, xl, wqh, wql, nullptr, nullptr, nullptr, nullptr, qkv, QKV_COLS, 1);

    // 5) fused attention -> ctx hi/lo (non-focus rows only)
    attn_kernel<<<B_SZ * S_LEN * NH, blk>>>(pbias);

    // 6) out: non-focus = ctx @ Wout, focus = x @ Wcomb (bf16x3)
    bgemm<<<dim3(DMODEL / 128, M_ROWS / 128), blk, SMEM_BYTES>>>(
        ch, cl, woh, wol, xh, xl, wch, wcl, out, DMODEL, 2);
}